// round 1
// baseline (speedup 1.0000x reference)
#include <cuda_runtime.h>
#include <cstdint>

#define POOL 14
#define IMG_H 200
#define IMG_W 200
#define IMG_C 1024
#define NUM_ROIS 512

// One block per (roi, py, px) pool cell. 256 threads * float4 = 1024 channels.
__global__ void __launch_bounds__(256, 8)
roi_resize_kernel(const float* __restrict__ img,
                  const int* __restrict__ rois,
                  float* __restrict__ out)
{
    const int idx  = blockIdx.x;                 // 0 .. 512*196-1
    const int roi  = idx / (POOL * POOL);
    const int cell = idx - roi * (POOL * POOL);
    const int py   = cell / POOL;
    const int px   = cell - py * POOL;

    // rois layout: [roi][4] = {x, y, w, h}, int32
    const int4 box = reinterpret_cast<const int4*>(rois)[roi];
    const int bx = box.x, by = box.y, bw = box.z, bh = box.w;

    // Match reference math: sy = py * (h / POOL), fraction from UNclipped floor.
    const float sy = (float)py * ((float)bh / (float)POOL);
    const float sx = (float)px * ((float)bw / (float)POOL);
    const int y0 = (int)floorf(sy);
    const int x0 = (int)floorf(sx);
    const float wy = sy - (float)y0;
    const float wx = sx - (float)x0;

    const int y0c = min(max(y0, 0), bh - 1);
    const int y1c = min(max(y0 + 1, 0), bh - 1);
    const int x0c = min(max(x0, 0), bw - 1);
    const int x1c = min(max(x0 + 1, 0), bw - 1);

    const int iy0 = by + y0c;
    const int iy1 = by + y1c;
    const int ix0 = bx + x0c;
    const int ix1 = bx + x1c;

    const float4* __restrict__ p00 =
        reinterpret_cast<const float4*>(img + ((size_t)iy0 * IMG_W + ix0) * IMG_C);
    const float4* __restrict__ p01 =
        reinterpret_cast<const float4*>(img + ((size_t)iy0 * IMG_W + ix1) * IMG_C);
    const float4* __restrict__ p10 =
        reinterpret_cast<const float4*>(img + ((size_t)iy1 * IMG_W + ix0) * IMG_C);
    const float4* __restrict__ p11 =
        reinterpret_cast<const float4*>(img + ((size_t)iy1 * IMG_W + ix1) * IMG_C);

    float4* __restrict__ o =
        reinterpret_cast<float4*>(out + (size_t)idx * IMG_C);

    const int c = threadIdx.x;   // 0..255 -> float4 lane

    const float4 g00 = p00[c];
    const float4 g01 = p01[c];
    const float4 g10 = p10[c];
    const float4 g11 = p11[c];

    float4 r;
    {
        float top, bot;
        top = g00.x + (g01.x - g00.x) * wx;
        bot = g10.x + (g11.x - g10.x) * wx;
        r.x = top + (bot - top) * wy;
        top = g00.y + (g01.y - g00.y) * wx;
        bot = g10.y + (g11.y - g10.y) * wx;
        r.y = top + (bot - top) * wy;
        top = g00.z + (g01.z - g00.z) * wx;
        bot = g10.z + (g11.z - g10.z) * wx;
        r.z = top + (bot - top) * wy;
        top = g00.w + (g01.w - g00.w) * wx;
        bot = g10.w + (g11.w - g10.w) * wx;
        r.w = top + (bot - top) * wy;
    }
    o[c] = r;
}

extern "C" void kernel_launch(void* const* d_in, const int* in_sizes, int n_in,
                              void* d_out, int out_size)
{
    // metadata order: img (40,960,000 f32), rois (2048 i32). Disambiguate by size.
    const float* img  = (const float*)d_in[0];
    const int*   rois = (const int*)d_in[1];
    if (in_sizes[0] == NUM_ROIS * 4) {  // swapped
        rois = (const int*)d_in[0];
        img  = (const float*)d_in[1];
    }
    float* out = (float*)d_out;

    const int blocks = NUM_ROIS * POOL * POOL;  // 100,352
    roi_resize_kernel<<<blocks, 256>>>(img, rois, out);
}